// round 14
// baseline (speedup 1.0000x reference)
#include <cuda_runtime.h>
#include <cstdint>

// Problem constants
#define E_   1024
#define H_   16
#define D_   64
#define B_   4
#define NQ_  4096
#define NK_  4096
#define MTOT (B_*NQ_)      // 16384 rows for all projections
#define BH_  (B_*H_)       // 64
#define NSPLIT 32          // split-K partitions for KV reduction

// ---------------- scratch (device globals; no allocation APIs) ----------------
__device__ float g_q[(size_t)MTOT * E_];      // Q projection (LN+elu'd in place)
__device__ float g_k[(size_t)MTOT * E_];      // K projection (LN+elu'd in place)
__device__ float g_v[(size_t)MTOT * E_];
__device__ float g_attn[(size_t)MTOT * E_];
__device__ float g_kvp[(size_t)NSPLIT * BH_ * D_ * D_];
__device__ float g_ksp[(size_t)NSPLIT * BH_ * D_];
__device__ float g_kv[(size_t)BH_ * D_ * D_];
__device__ float g_ksum[(size_t)BH_ * D_];

// =====================================================================
// Helpers (sm_80+ base target features only)
// =====================================================================
__device__ __forceinline__ uint32_t smem_u32(const void* p) {
    uint32_t a;
    asm("{ .reg .u64 t; cvta.to.shared.u64 t, %1; cvt.u32.u64 %0, t; }"
        : "=r"(a) : "l"(p));
    return a;
}

__device__ __forceinline__ void cp_async16(uint32_t saddr, const void* gaddr) {
    asm volatile("cp.async.cg.shared.global [%0], [%1], 16;"
                 :: "r"(saddr), "l"(gaddr));
}
__device__ __forceinline__ void cp_commit() {
    asm volatile("cp.async.commit_group;" ::: "memory");
}
template <int N>
__device__ __forceinline__ void cp_wait() {
    asm volatile("cp.async.wait_group %0;" :: "n"(N) : "memory");
}

__device__ __forceinline__ uint32_t f2tf32(float f) {
    uint32_t u;
    asm("cvt.rna.tf32.f32 %0, %1;" : "=r"(u) : "f"(f));
    return u;
}

__device__ __forceinline__ void mma_tf32(
    float& d0, float& d1, float& d2, float& d3,
    uint32_t a0, uint32_t a1, uint32_t a2, uint32_t a3,
    uint32_t b0, uint32_t b1)
{
    asm volatile(
        "mma.sync.aligned.m16n8k8.row.col.f32.tf32.tf32.f32 "
        "{%0,%1,%2,%3}, {%4,%5,%6,%7}, {%8,%9}, {%0,%1,%2,%3};"
        : "+f"(d0), "+f"(d1), "+f"(d2), "+f"(d3)
        : "r"(a0), "r"(a1), "r"(a2), "r"(a3), "r"(b0), "r"(b1));
}

// =====================================================================
// tf32 GEMM (round-7 kernel, byte-exact): C[m,n]=sum_k X[m,k]W[n,k]+bias[n]
// =====================================================================
#define BM 128
#define BN 128
#define BK 32
#define NKT (E_/BK)
#define ASTR 36
#define TILEF (128*ASTR)
#define GEMM_SMEM (4*TILEF*4)   // 73728 bytes

__global__ void __launch_bounds__(256, 2)
gemm_mma_kernel(const float* __restrict__ X, const float* __restrict__ W,
                const float* __restrict__ bias, float* __restrict__ C)
{
    extern __shared__ float smf[];
    const uint32_t sbase = smem_u32(smf);
    const int tid = threadIdx.x;
    const int wid = tid >> 5;
    const int lane = tid & 31;
    const int g  = lane >> 2;
    const int t4 = lane & 3;
    const int wm = (wid >> 2) * 64;
    const int wn = (wid & 3) * 32;
    const int bm = blockIdx.x * BM;
    const int bn = blockIdx.y * BN;

    const int srow = tid >> 3;
    const int sc4  = (tid & 7) * 4;

    float acc[4][4][4];
#pragma unroll
    for (int i = 0; i < 4; i++)
#pragma unroll
        for (int j = 0; j < 4; j++)
#pragma unroll
            for (int r = 0; r < 4; r++) acc[i][j][r] = 0.0f;

    auto prefetch = [&](int kt, int buf) {
        const int k0 = kt * BK;
        const uint32_t aoff = sbase + (uint32_t)(buf * TILEF) * 4u;
        const uint32_t boff = sbase + (uint32_t)((2 + buf) * TILEF) * 4u;
#pragma unroll
        for (int l = 0; l < 4; l++) {
            int row = srow + l * 32;
            cp_async16(aoff + (row * ASTR + sc4) * 4,
                       X + (size_t)(bm + row) * E_ + k0 + sc4);
            cp_async16(boff + (row * ASTR + sc4) * 4,
                       W + (size_t)(bn + row) * E_ + k0 + sc4);
        }
        cp_commit();
    };

    prefetch(0, 0);

    for (int kt = 0; kt < NKT; kt++) {
        const int buf = kt & 1;
        if (kt + 1 < NKT) {
            prefetch(kt + 1, buf ^ 1);
            cp_wait<1>();
        } else {
            cp_wait<0>();
        }
        __syncthreads();

        const float* As = smf + buf * TILEF;
        const float* Bs = smf + (2 + buf) * TILEF;

#pragma unroll
        for (int ks = 0; ks < 4; ks++) {
            const int kk = ks * 8;
            uint32_t bf[4][2];
#pragma unroll
            for (int nf = 0; nf < 4; nf++) {
                const float* bp = Bs + (wn + nf * 8 + g) * ASTR + kk + t4;
                bf[nf][0] = f2tf32(bp[0]);
                bf[nf][1] = f2tf32(bp[4]);
            }
#pragma unroll
            for (int mf = 0; mf < 4; mf++) {
                const float* ap = As + (wm + mf * 16 + g) * ASTR + kk + t4;
                uint32_t a0 = f2tf32(ap[0]);
                uint32_t a1 = f2tf32(ap[8 * ASTR]);
                uint32_t a2 = f2tf32(ap[4]);
                uint32_t a3 = f2tf32(ap[8 * ASTR + 4]);
#pragma unroll
                for (int nf = 0; nf < 4; nf++)
                    mma_tf32(acc[mf][nf][0], acc[mf][nf][1],
                             acc[mf][nf][2], acc[mf][nf][3],
                             a0, a1, a2, a3, bf[nf][0], bf[nf][1]);
            }
        }
        __syncthreads();
    }

#pragma unroll
    for (int nf = 0; nf < 4; nf++) {
        const int col = bn + wn + nf * 8 + t4 * 2;
        const float2 b2 = *(const float2*)(bias + col);
#pragma unroll
        for (int mf = 0; mf < 4; mf++) {
            const int row0 = bm + wm + mf * 16 + g;
            float2 v0, v1;
            v0.x = acc[mf][nf][0] + b2.x;
            v0.y = acc[mf][nf][1] + b2.y;
            v1.x = acc[mf][nf][2] + b2.x;
            v1.y = acc[mf][nf][3] + b2.y;
            *(float2*)(C + (size_t)row0 * E_ + col) = v0;
            *(float2*)(C + (size_t)(row0 + 8) * E_ + col) = v1;
        }
    }
}

// ---------------- LayerNorm + elu + 1 body (one block per row) ----------------
__device__ __forceinline__ void ln_body(float* __restrict__ xr,
                                        const float* __restrict__ gamma,
                                        const float* __restrict__ beta)
{
    const int t = threadIdx.x;
    float v[4];
#pragma unroll
    for (int i = 0; i < 4; i++) v[i] = xr[t + i * 256];

    __shared__ float red[8];
    float s = v[0] + v[1] + v[2] + v[3];
#pragma unroll
    for (int o = 16; o > 0; o >>= 1) s += __shfl_xor_sync(0xffffffffu, s, o);
    if ((t & 31) == 0) red[t >> 5] = s;
    __syncthreads();
    float tot = red[0] + red[1] + red[2] + red[3] + red[4] + red[5] + red[6] + red[7];
    float mean = tot * (1.0f / E_);
    __syncthreads();

    float d0 = v[0] - mean, d1 = v[1] - mean, d2 = v[2] - mean, d3 = v[3] - mean;
    float s2 = d0 * d0 + d1 * d1 + d2 * d2 + d3 * d3;
#pragma unroll
    for (int o = 16; o > 0; o >>= 1) s2 += __shfl_xor_sync(0xffffffffu, s2, o);
    if ((t & 31) == 0) red[t >> 5] = s2;
    __syncthreads();
    float var = (red[0] + red[1] + red[2] + red[3] + red[4] + red[5] + red[6] + red[7]) * (1.0f / E_);
    float rstd = rsqrtf(var + 1e-5f);

    float dd[4] = {d0, d1, d2, d3};
#pragma unroll
    for (int i = 0; i < 4; i++) {
        int col = t + i * 256;
        float y = dd[i] * rstd * gamma[col] + beta[col];
        xr[col] = (y > 0.0f) ? (y + 1.0f) : expf(y);
    }
}

__global__ __launch_bounds__(256)
void ln_elu_kernel(float* __restrict__ X, const float* __restrict__ gamma,
                   const float* __restrict__ beta) {
    ln_body(X + (size_t)blockIdx.x * E_, gamma, beta);
}

// ---------------- KV reduction (round-4 SIMT, measured ~47us) ----------------
__global__ __launch_bounds__(256)
void kv_kernel() {
    const int bh = blockIdx.x;
    const int b = bh >> 4, h = bh & 15;
    const int split = blockIdx.y;
    const int t = threadIdx.x;
    const int tx = t & 15, ty = t >> 4;

    __shared__ float Ks[64][68];
    __shared__ float Vs[64][68];

    const float* kbase = g_k + (size_t)(b * NK_) * E_ + h * D_;
    const float* vbase = g_v + (size_t)(b * NK_) * E_ + h * D_;

    float acc[4][4];
#pragma unroll
    for (int i = 0; i < 4; i++)
#pragma unroll
        for (int j = 0; j < 4; j++) acc[i][j] = 0.0f;
    float ks_local = 0.0f;

    for (int sblk = 0; sblk < 2; sblk++) {
        int n0 = split * 128 + sblk * 64;
#pragma unroll
        for (int l = 0; l < 4; l++) {
            int lin = t + l * 256;
            int r = lin >> 4;
            int c4 = (lin & 15) * 4;
            *(float4*)&Ks[r][c4] = *(const float4*)(kbase + (size_t)(n0 + r) * E_ + c4);
            *(float4*)&Vs[r][c4] = *(const float4*)(vbase + (size_t)(n0 + r) * E_ + c4);
        }
        __syncthreads();
#pragma unroll 4
        for (int n = 0; n < 64; n++) {
            float a[4], bb[4];
            *(float4*)a  = *(const float4*)&Ks[n][ty * 4];
            *(float4*)bb = *(const float4*)&Vs[n][tx * 4];
#pragma unroll
            for (int i = 0; i < 4; i++)
#pragma unroll
                for (int j = 0; j < 4; j++)
                    acc[i][j] += a[i] * bb[j];
        }
        if (t < 64) {
            float ss = 0.0f;
#pragma unroll 4
            for (int n = 0; n < 64; n++) ss += Ks[n][t];
            ks_local += ss;
        }
        __syncthreads();
    }

    float* outp = g_kvp + ((size_t)(split * BH_ + bh)) * (D_ * D_);
#pragma unroll
    for (int i = 0; i < 4; i++)
#pragma unroll
        for (int j = 0; j < 4; j++)
            outp[(ty * 4 + i) * D_ + tx * 4 + j] = acc[i][j];
    if (t < 64) g_ksp[(size_t)(split * BH_ + bh) * D_ + t] = ks_local;
}

// ---------------- merged: reduce split-K partials ∥ LN+elu on Q ----------------
#define NRED_CTAS ((BH_*D_*D_ + BH_*D_) / 256)   // 1040
__global__ __launch_bounds__(256)
void reduce_ln_kernel(float* __restrict__ Qx, const float* __restrict__ gq,
                      const float* __restrict__ betaq)
{
    if (blockIdx.x < NRED_CTAS) {
        int idx = blockIdx.x * 256 + threadIdx.x;
        const int NKV = BH_ * D_ * D_;
        const int NKS = BH_ * D_;
        if (idx < NKV) {
            float s = 0.0f;
#pragma unroll
            for (int sp = 0; sp < NSPLIT; sp++)
                s += g_kvp[(size_t)sp * NKV + idx];
            g_kv[idx] = s;
        } else if (idx < NKV + NKS) {
            int j = idx - NKV;
            float s = 0.0f;
#pragma unroll
            for (int sp = 0; sp < NSPLIT; sp++)
                s += g_ksp[(size_t)sp * NKS + j];
            g_ksum[j] = s;
        }
    } else {
        ln_body(Qx + (size_t)(blockIdx.x - NRED_CTAS) * E_, gq, betaq);
    }
}

// =====================================================================
// Attention apply via tensor cores (round-13, measured fast):
// per (b,h), 64-row q-tile: num = Q'[64x64] @ KV[64x64], den = Q'.ksum
// =====================================================================
#define QSTR 68

__global__ void __launch_bounds__(256)
attn_mma_kernel()
{
    __shared__ float Qs[64 * QSTR];
    __shared__ float KVT[64 * QSTR];
    __shared__ float ksums[64];

    const int bh = blockIdx.x;
    const int b = bh >> 4, h = bh & 15;
    const int n0 = blockIdx.y * 64;
    const int t = threadIdx.x;
    const int wid = t >> 5, lane = t & 31;
    const int g = lane >> 2, t4 = lane & 3;
    const int wq = wid >> 1;
    const int wn = (wid & 1) * 32;

    if (t < 64) ksums[t] = g_ksum[(size_t)bh * D_ + t];

#pragma unroll
    for (int l = 0; l < 4; l++) {
        int lin = t + l * 256;
        int r = lin >> 4;
        int c4 = (lin & 15) * 4;
        *(float4*)&Qs[r * QSTR + c4] =
            *(const float4*)(g_q + (size_t)(b * NQ_ + n0 + r) * E_ + h * D_ + c4);
    }
#pragma unroll
    for (int l = 0; l < 4; l++) {
        int lin = t + l * 256;
        int rd = lin >> 4;
        int c4 = (lin & 15) * 4;
        float4 kvx = *(const float4*)(g_kv + (size_t)bh * (D_ * D_) + rd * D_ + c4);
        KVT[(c4 + 0) * QSTR + rd] = kvx.x;
        KVT[(c4 + 1) * QSTR + rd] = kvx.y;
        KVT[(c4 + 2) * QSTR + rd] = kvx.z;
        KVT[(c4 + 3) * QSTR + rd] = kvx.w;
    }
    __syncthreads();

    float acc[4][4];
#pragma unroll
    for (int j = 0; j < 4; j++)
#pragma unroll
        for (int r = 0; r < 4; r++) acc[j][r] = 0.0f;

#pragma unroll
    for (int ks = 0; ks < 8; ks++) {
        const int kk = ks * 8;
        const float* ap = &Qs[(wq * 16 + g) * QSTR + kk + t4];
        uint32_t a0 = f2tf32(ap[0]);
        uint32_t a1 = f2tf32(ap[8 * QSTR]);
        uint32_t a2 = f2tf32(ap[4]);
        uint32_t a3 = f2tf32(ap[8 * QSTR + 4]);
#pragma unroll
        for (int nf = 0; nf < 4; nf++) {
            const float* bp = &KVT[(wn + nf * 8 + g) * QSTR + kk + t4];
            mma_tf32(acc[nf][0], acc[nf][1], acc[nf][2], acc[nf][3],
                     a0, a1, a2, a3, f2tf32(bp[0]), f2tf32(bp[4]));
        }
    }

    const int r0 = wq * 16 + g, r1 = r0 + 8;
    float dp0 = 0.0f, dp1 = 0.0f;
#pragma unroll
    for (int i = 0; i < 16; i++) {
        int d = t4 * 16 + i;
        float kd = ksums[d];
        dp0 += Qs[r0 * QSTR + d] * kd;
        dp1 += Qs[r1 * QSTR + d] * kd;
    }
    dp0 += __shfl_xor_sync(0xffffffffu, dp0, 1);
    dp0 += __shfl_xor_sync(0xffffffffu, dp0, 2);
    dp1 += __shfl_xor_sync(0xffffffffu, dp1, 1);
    dp1 += __shfl_xor_sync(0xffffffffu, dp1, 2);
    const float inv0 = 1.0f / (dp0 + 1e-8f);
    const float inv1 = 1.0f / (dp1 + 1e-8f);

#pragma unroll
    for (int nf = 0; nf < 4; nf++) {
        const int e0 = wn + nf * 8 + t4 * 2;
        float2 o0, o1;
        o0.x = acc[nf][0] * inv0; o0.y = acc[nf][1] * inv0;
        o1.x = acc[nf][2] * inv1; o1.y = acc[nf][3] * inv1;
        *(float2*)(g_attn + (size_t)(b * NQ_ + n0 + r0) * E_ + h * D_ + e0) = o0;
        *(float2*)(g_attn + (size_t)(b * NQ_ + n0 + r1) * E_ + h * D_ + e0) = o1;
    }
}

// ---------------- host launcher ----------------
extern "C" void kernel_launch(void* const* d_in, const int* in_sizes, int n_in,
                              void* d_out, int out_size) {
    (void)in_sizes; (void)n_in; (void)out_size;
    const float* query = (const float*)d_in[0];
    const float* key   = (const float*)d_in[1];
    const float* value = (const float*)d_in[2];
    const float* Wq = (const float*)d_in[3];
    const float* bq = (const float*)d_in[4];
    const float* Wk = (const float*)d_in[5];
    const float* bk = (const float*)d_in[6];
    const float* Wv = (const float*)d_in[7];
    const float* bv = (const float*)d_in[8];
    const float* Wo = (const float*)d_in[9];
    const float* bo = (const float*)d_in[10];
    const float* gq    = (const float*)d_in[11];
    const float* betaq = (const float*)d_in[12];
    const float* gk    = (const float*)d_in[13];
    const float* betak = (const float*)d_in[14];
    float* out = (float*)d_out;

    float *pq, *pk, *pv, *pattn;
    cudaGetSymbolAddress((void**)&pq, g_q);
    cudaGetSymbolAddress((void**)&pk, g_k);
    cudaGetSymbolAddress((void**)&pv, g_v);
    cudaGetSymbolAddress((void**)&pattn, g_attn);

    cudaFuncSetAttribute(gemm_mma_kernel,
                         cudaFuncAttributeMaxDynamicSharedMemorySize, GEMM_SMEM);

    dim3 ggrid(MTOT / BM, E_ / BN);   // (128, 8)

    // K projection + LN+elu (in place)
    gemm_mma_kernel<<<ggrid, 256, GEMM_SMEM>>>(key, Wk, bk, pk);
    ln_elu_kernel<<<MTOT, 256>>>(pk, gk, betak);
    // V projection
    gemm_mma_kernel<<<ggrid, 256, GEMM_SMEM>>>(value, Wv, bv, pv);
    // KV split-K partials (SIMT, round-4 version)
    kv_kernel<<<dim3(BH_, NSPLIT), 256>>>();
    // Q projection
    gemm_mma_kernel<<<ggrid, 256, GEMM_SMEM>>>(query, Wq, bq, pq);
    // merged: reduce split-K partials ∥ LN+elu on Q (both small-smem)
    reduce_ln_kernel<<<NRED_CTAS + MTOT, 256>>>(pq, gq, betaq);
    // attention apply (tensor-core)
    attn_mma_kernel<<<dim3(BH_, NQ_ / 64), 256>>>();
    // output projection -> d_out
    gemm_mma_kernel<<<ggrid, 256, GEMM_SMEM>>>(pattn, Wo, bo, out);
}

// round 15
// speedup vs baseline: 1.0411x; 1.0411x over previous
#include <cuda_runtime.h>
#include <cstdint>

// Problem constants
#define E_   1024
#define H_   16
#define D_   64
#define B_   4
#define NQ_  4096
#define NK_  4096
#define MTOT (B_*NQ_)      // 16384 rows for all projections
#define BH_  (B_*H_)       // 64
#define NSPLIT 32          // split-K partitions for KV reduction

// ---------------- scratch (device globals; no allocation APIs) ----------------
__device__ float g_q[(size_t)MTOT * E_];      // Q projection (LN+elu'd in place)
__device__ float g_k[(size_t)MTOT * E_];      // K projection (LN+elu'd in place)
__device__ float g_v[(size_t)MTOT * E_];
__device__ float g_attn[(size_t)MTOT * E_];
__device__ float g_kvp[(size_t)NSPLIT * BH_ * D_ * D_];
__device__ float g_ksp[(size_t)NSPLIT * BH_ * D_];
__device__ float g_kv[(size_t)BH_ * D_ * D_];
__device__ float g_ksum[(size_t)BH_ * D_];

// =====================================================================
// Helpers (sm_80+ base target features only)
// =====================================================================
__device__ __forceinline__ uint32_t smem_u32(const void* p) {
    uint32_t a;
    asm("{ .reg .u64 t; cvta.to.shared.u64 t, %1; cvt.u32.u64 %0, t; }"
        : "=r"(a) : "l"(p));
    return a;
}

__device__ __forceinline__ void cp_async16(uint32_t saddr, const void* gaddr) {
    asm volatile("cp.async.cg.shared.global [%0], [%1], 16;"
                 :: "r"(saddr), "l"(gaddr));
}
__device__ __forceinline__ void cp_commit() {
    asm volatile("cp.async.commit_group;" ::: "memory");
}
template <int N>
__device__ __forceinline__ void cp_wait() {
    asm volatile("cp.async.wait_group %0;" :: "n"(N) : "memory");
}

__device__ __forceinline__ uint32_t f2tf32(float f) {
    uint32_t u;
    asm("cvt.rna.tf32.f32 %0, %1;" : "=r"(u) : "f"(f));
    return u;
}

__device__ __forceinline__ void mma_tf32(
    float& d0, float& d1, float& d2, float& d3,
    uint32_t a0, uint32_t a1, uint32_t a2, uint32_t a3,
    uint32_t b0, uint32_t b1)
{
    asm volatile(
        "mma.sync.aligned.m16n8k8.row.col.f32.tf32.tf32.f32 "
        "{%0,%1,%2,%3}, {%4,%5,%6,%7}, {%8,%9}, {%0,%1,%2,%3};"
        : "+f"(d0), "+f"(d1), "+f"(d2), "+f"(d3)
        : "r"(a0), "r"(a1), "r"(a2), "r"(a3), "r"(b0), "r"(b1));
}

// =====================================================================
// tf32 GEMM (round-7 kernel, byte-exact): C[m,n]=sum_k X[m,k]W[n,k]+bias[n]
// =====================================================================
#define BM 128
#define BN 128
#define BK 32
#define NKT (E_/BK)
#define ASTR 36
#define TILEF (128*ASTR)
#define GEMM_SMEM (4*TILEF*4)   // 73728 bytes

__global__ void __launch_bounds__(256, 2)
gemm_mma_kernel(const float* __restrict__ X, const float* __restrict__ W,
                const float* __restrict__ bias, float* __restrict__ C)
{
    extern __shared__ float smf[];
    const uint32_t sbase = smem_u32(smf);
    const int tid = threadIdx.x;
    const int wid = tid >> 5;
    const int lane = tid & 31;
    const int g  = lane >> 2;
    const int t4 = lane & 3;
    const int wm = (wid >> 2) * 64;
    const int wn = (wid & 3) * 32;
    const int bm = blockIdx.x * BM;
    const int bn = blockIdx.y * BN;

    const int srow = tid >> 3;
    const int sc4  = (tid & 7) * 4;

    float acc[4][4][4];
#pragma unroll
    for (int i = 0; i < 4; i++)
#pragma unroll
        for (int j = 0; j < 4; j++)
#pragma unroll
            for (int r = 0; r < 4; r++) acc[i][j][r] = 0.0f;

    auto prefetch = [&](int kt, int buf) {
        const int k0 = kt * BK;
        const uint32_t aoff = sbase + (uint32_t)(buf * TILEF) * 4u;
        const uint32_t boff = sbase + (uint32_t)((2 + buf) * TILEF) * 4u;
#pragma unroll
        for (int l = 0; l < 4; l++) {
            int row = srow + l * 32;
            cp_async16(aoff + (row * ASTR + sc4) * 4,
                       X + (size_t)(bm + row) * E_ + k0 + sc4);
            cp_async16(boff + (row * ASTR + sc4) * 4,
                       W + (size_t)(bn + row) * E_ + k0 + sc4);
        }
        cp_commit();
    };

    prefetch(0, 0);

    for (int kt = 0; kt < NKT; kt++) {
        const int buf = kt & 1;
        if (kt + 1 < NKT) {
            prefetch(kt + 1, buf ^ 1);
            cp_wait<1>();
        } else {
            cp_wait<0>();
        }
        __syncthreads();

        const float* As = smf + buf * TILEF;
        const float* Bs = smf + (2 + buf) * TILEF;

#pragma unroll
        for (int ks = 0; ks < 4; ks++) {
            const int kk = ks * 8;
            uint32_t bf[4][2];
#pragma unroll
            for (int nf = 0; nf < 4; nf++) {
                const float* bp = Bs + (wn + nf * 8 + g) * ASTR + kk + t4;
                bf[nf][0] = f2tf32(bp[0]);
                bf[nf][1] = f2tf32(bp[4]);
            }
#pragma unroll
            for (int mf = 0; mf < 4; mf++) {
                const float* ap = As + (wm + mf * 16 + g) * ASTR + kk + t4;
                uint32_t a0 = f2tf32(ap[0]);
                uint32_t a1 = f2tf32(ap[8 * ASTR]);
                uint32_t a2 = f2tf32(ap[4]);
                uint32_t a3 = f2tf32(ap[8 * ASTR + 4]);
#pragma unroll
                for (int nf = 0; nf < 4; nf++)
                    mma_tf32(acc[mf][nf][0], acc[mf][nf][1],
                             acc[mf][nf][2], acc[mf][nf][3],
                             a0, a1, a2, a3, bf[nf][0], bf[nf][1]);
            }
        }
        __syncthreads();
    }

#pragma unroll
    for (int nf = 0; nf < 4; nf++) {
        const int col = bn + wn + nf * 8 + t4 * 2;
        const float2 b2 = *(const float2*)(bias + col);
#pragma unroll
        for (int mf = 0; mf < 4; mf++) {
            const int row0 = bm + wm + mf * 16 + g;
            float2 v0, v1;
            v0.x = acc[mf][nf][0] + b2.x;
            v0.y = acc[mf][nf][1] + b2.y;
            v1.x = acc[mf][nf][2] + b2.x;
            v1.y = acc[mf][nf][3] + b2.y;
            *(float2*)(C + (size_t)row0 * E_ + col) = v0;
            *(float2*)(C + (size_t)(row0 + 8) * E_ + col) = v1;
        }
    }
}

// ---------------- LayerNorm + elu + 1 (one block per row) ----------------
__global__ __launch_bounds__(256)
void ln_elu_kernel(float* __restrict__ X, const float* __restrict__ gamma,
                   const float* __restrict__ beta) {
    const int row = blockIdx.x;
    const int t = threadIdx.x;
    float* xr = X + (size_t)row * E_;

    float v[4];
#pragma unroll
    for (int i = 0; i < 4; i++) v[i] = xr[t + i * 256];

    __shared__ float red[8];
    float s = v[0] + v[1] + v[2] + v[3];
#pragma unroll
    for (int o = 16; o > 0; o >>= 1) s += __shfl_xor_sync(0xffffffffu, s, o);
    if ((t & 31) == 0) red[t >> 5] = s;
    __syncthreads();
    float tot = red[0] + red[1] + red[2] + red[3] + red[4] + red[5] + red[6] + red[7];
    float mean = tot * (1.0f / E_);
    __syncthreads();

    float d0 = v[0] - mean, d1 = v[1] - mean, d2 = v[2] - mean, d3 = v[3] - mean;
    float s2 = d0 * d0 + d1 * d1 + d2 * d2 + d3 * d3;
#pragma unroll
    for (int o = 16; o > 0; o >>= 1) s2 += __shfl_xor_sync(0xffffffffu, s2, o);
    if ((t & 31) == 0) red[t >> 5] = s2;
    __syncthreads();
    float var = (red[0] + red[1] + red[2] + red[3] + red[4] + red[5] + red[6] + red[7]) * (1.0f / E_);
    float rstd = rsqrtf(var + 1e-5f);

    float dd[4] = {d0, d1, d2, d3};
#pragma unroll
    for (int i = 0; i < 4; i++) {
        int col = t + i * 256;
        float y = dd[i] * rstd * gamma[col] + beta[col];
        xr[col] = (y > 0.0f) ? (y + 1.0f) : expf(y);
    }
}

// ---------------- KV reduction (SIMT; runs concurrently with GEMMs) ----------------
__global__ __launch_bounds__(256)
void kv_kernel() {
    const int bh = blockIdx.x;
    const int b = bh >> 4, h = bh & 15;
    const int split = blockIdx.y;
    const int t = threadIdx.x;
    const int tx = t & 15, ty = t >> 4;

    __shared__ float Ks[64][68];
    __shared__ float Vs[64][68];

    const float* kbase = g_k + (size_t)(b * NK_) * E_ + h * D_;
    const float* vbase = g_v + (size_t)(b * NK_) * E_ + h * D_;

    float acc[4][4];
#pragma unroll
    for (int i = 0; i < 4; i++)
#pragma unroll
        for (int j = 0; j < 4; j++) acc[i][j] = 0.0f;
    float ks_local = 0.0f;

    for (int sblk = 0; sblk < 2; sblk++) {
        int n0 = split * 128 + sblk * 64;
#pragma unroll
        for (int l = 0; l < 4; l++) {
            int lin = t + l * 256;
            int r = lin >> 4;
            int c4 = (lin & 15) * 4;
            *(float4*)&Ks[r][c4] = *(const float4*)(kbase + (size_t)(n0 + r) * E_ + c4);
            *(float4*)&Vs[r][c4] = *(const float4*)(vbase + (size_t)(n0 + r) * E_ + c4);
        }
        __syncthreads();
#pragma unroll 4
        for (int n = 0; n < 64; n++) {
            float a[4], bb[4];
            *(float4*)a  = *(const float4*)&Ks[n][ty * 4];
            *(float4*)bb = *(const float4*)&Vs[n][tx * 4];
#pragma unroll
            for (int i = 0; i < 4; i++)
#pragma unroll
                for (int j = 0; j < 4; j++)
                    acc[i][j] += a[i] * bb[j];
        }
        if (t < 64) {
            float ss = 0.0f;
#pragma unroll 4
            for (int n = 0; n < 64; n++) ss += Ks[n][t];
            ks_local += ss;
        }
        __syncthreads();
    }

    float* outp = g_kvp + ((size_t)(split * BH_ + bh)) * (D_ * D_);
#pragma unroll
    for (int i = 0; i < 4; i++)
#pragma unroll
        for (int j = 0; j < 4; j++)
            outp[(ty * 4 + i) * D_ + tx * 4 + j] = acc[i][j];
    if (t < 64) g_ksp[(size_t)(split * BH_ + bh) * D_ + t] = ks_local;
}

// ---------------- reduce split-K partials ----------------
__global__ __launch_bounds__(256)
void reduce_kv_kernel() {
    int idx = blockIdx.x * blockDim.x + threadIdx.x;
    const int NKV = BH_ * D_ * D_;
    const int NKS = BH_ * D_;
    if (idx < NKV) {
        float s = 0.0f;
#pragma unroll
        for (int sp = 0; sp < NSPLIT; sp++)
            s += g_kvp[(size_t)sp * NKV + idx];
        g_kv[idx] = s;
    } else if (idx < NKV + NKS) {
        int j = idx - NKV;
        float s = 0.0f;
#pragma unroll
        for (int sp = 0; sp < NSPLIT; sp++)
            s += g_ksp[(size_t)sp * NKS + j];
        g_ksum[j] = s;
    }
}

// =====================================================================
// Attention apply via tensor cores (round-13):
// per (b,h), 64-row q-tile: num = Q'[64x64] @ KV[64x64], den = Q'.ksum
// =====================================================================
#define QSTR 68

__global__ void __launch_bounds__(256)
attn_mma_kernel()
{
    __shared__ float Qs[64 * QSTR];
    __shared__ float KVT[64 * QSTR];
    __shared__ float ksums[64];

    const int bh = blockIdx.x;
    const int b = bh >> 4, h = bh & 15;
    const int n0 = blockIdx.y * 64;
    const int t = threadIdx.x;
    const int wid = t >> 5, lane = t & 31;
    const int g = lane >> 2, t4 = lane & 3;
    const int wq = wid >> 1;
    const int wn = (wid & 1) * 32;

    if (t < 64) ksums[t] = g_ksum[(size_t)bh * D_ + t];

#pragma unroll
    for (int l = 0; l < 4; l++) {
        int lin = t + l * 256;
        int r = lin >> 4;
        int c4 = (lin & 15) * 4;
        *(float4*)&Qs[r * QSTR + c4] =
            *(const float4*)(g_q + (size_t)(b * NQ_ + n0 + r) * E_ + h * D_ + c4);
    }
#pragma unroll
    for (int l = 0; l < 4; l++) {
        int lin = t + l * 256;
        int rd = lin >> 4;
        int c4 = (lin & 15) * 4;
        float4 kvx = *(const float4*)(g_kv + (size_t)bh * (D_ * D_) + rd * D_ + c4);
        KVT[(c4 + 0) * QSTR + rd] = kvx.x;
        KVT[(c4 + 1) * QSTR + rd] = kvx.y;
        KVT[(c4 + 2) * QSTR + rd] = kvx.z;
        KVT[(c4 + 3) * QSTR + rd] = kvx.w;
    }
    __syncthreads();

    float acc[4][4];
#pragma unroll
    for (int j = 0; j < 4; j++)
#pragma unroll
        for (int r = 0; r < 4; r++) acc[j][r] = 0.0f;

#pragma unroll
    for (int ks = 0; ks < 8; ks++) {
        const int kk = ks * 8;
        const float* ap = &Qs[(wq * 16 + g) * QSTR + kk + t4];
        uint32_t a0 = f2tf32(ap[0]);
        uint32_t a1 = f2tf32(ap[8 * QSTR]);
        uint32_t a2 = f2tf32(ap[4]);
        uint32_t a3 = f2tf32(ap[8 * QSTR + 4]);
#pragma unroll
        for (int nf = 0; nf < 4; nf++) {
            const float* bp = &KVT[(wn + nf * 8 + g) * QSTR + kk + t4];
            mma_tf32(acc[nf][0], acc[nf][1], acc[nf][2], acc[nf][3],
                     a0, a1, a2, a3, f2tf32(bp[0]), f2tf32(bp[4]));
        }
    }

    const int r0 = wq * 16 + g, r1 = r0 + 8;
    float dp0 = 0.0f, dp1 = 0.0f;
#pragma unroll
    for (int i = 0; i < 16; i++) {
        int d = t4 * 16 + i;
        float kd = ksums[d];
        dp0 += Qs[r0 * QSTR + d] * kd;
        dp1 += Qs[r1 * QSTR + d] * kd;
    }
    dp0 += __shfl_xor_sync(0xffffffffu, dp0, 1);
    dp0 += __shfl_xor_sync(0xffffffffu, dp0, 2);
    dp1 += __shfl_xor_sync(0xffffffffu, dp1, 1);
    dp1 += __shfl_xor_sync(0xffffffffu, dp1, 2);
    const float inv0 = 1.0f / (dp0 + 1e-8f);
    const float inv1 = 1.0f / (dp1 + 1e-8f);

#pragma unroll
    for (int nf = 0; nf < 4; nf++) {
        const int e0 = wn + nf * 8 + t4 * 2;
        float2 o0, o1;
        o0.x = acc[nf][0] * inv0; o0.y = acc[nf][1] * inv0;
        o1.x = acc[nf][2] * inv1; o1.y = acc[nf][3] * inv1;
        *(float2*)(g_attn + (size_t)(b * NQ_ + n0 + r0) * E_ + h * D_ + e0) = o0;
        *(float2*)(g_attn + (size_t)(b * NQ_ + n0 + r1) * E_ + h * D_ + e0) = o1;
    }
}

// ---------------- host launcher (fork/join side stream) ----------------
extern "C" void kernel_launch(void* const* d_in, const int* in_sizes, int n_in,
                              void* d_out, int out_size) {
    (void)in_sizes; (void)n_in; (void)out_size;
    const float* query = (const float*)d_in[0];
    const float* key   = (const float*)d_in[1];
    const float* value = (const float*)d_in[2];
    const float* Wq = (const float*)d_in[3];
    const float* bq = (const float*)d_in[4];
    const float* Wk = (const float*)d_in[5];
    const float* bk = (const float*)d_in[6];
    const float* Wv = (const float*)d_in[7];
    const float* bv = (const float*)d_in[8];
    const float* Wo = (const float*)d_in[9];
    const float* bo = (const float*)d_in[10];
    const float* gq    = (const float*)d_in[11];
    const float* betaq = (const float*)d_in[12];
    const float* gk    = (const float*)d_in[13];
    const float* betak = (const float*)d_in[14];
    float* out = (float*)d_out;

    float *pq, *pk, *pv, *pattn;
    cudaGetSymbolAddress((void**)&pq, g_q);
    cudaGetSymbolAddress((void**)&pk, g_k);
    cudaGetSymbolAddress((void**)&pv, g_v);
    cudaGetSymbolAddress((void**)&pattn, g_attn);

    cudaFuncSetAttribute(gemm_mma_kernel,
                         cudaFuncAttributeMaxDynamicSharedMemorySize, GEMM_SMEM);

    // One-time resource init (first call is the non-capturing correctness
    // run; work launched per call is identical every time).
    static cudaStream_t s2 = nullptr;
    static cudaEvent_t ev_k = nullptr, ev_v = nullptr, ev_side = nullptr;
    if (s2 == nullptr) {
        cudaStreamCreateWithFlags(&s2, cudaStreamNonBlocking);
        cudaEventCreateWithFlags(&ev_k, cudaEventDisableTiming);
        cudaEventCreateWithFlags(&ev_v, cudaEventDisableTiming);
        cudaEventCreateWithFlags(&ev_side, cudaEventDisableTiming);
    }

    dim3 ggrid(MTOT / BM, E_ / BN);   // (128, 8)

    // Main: K projection
    gemm_mma_kernel<<<ggrid, 256, GEMM_SMEM>>>(key, Wk, bk, pk);
    cudaEventRecord(ev_k, 0);
    // Main: V projection (concurrent with side ln_k)
    gemm_mma_kernel<<<ggrid, 256, GEMM_SMEM>>>(value, Wv, bv, pv);
    cudaEventRecord(ev_v, 0);

    // Side: ln_k after K-GEMM; kv after V-GEMM; reduce after kv
    cudaStreamWaitEvent(s2, ev_k, 0);
    ln_elu_kernel<<<MTOT, 256, 0, s2>>>(pk, gk, betak);
    cudaStreamWaitEvent(s2, ev_v, 0);
    kv_kernel<<<dim3(BH_, NSPLIT), 256, 0, s2>>>();
    reduce_kv_kernel<<<(BH_ * D_ * D_ + BH_ * D_ + 255) / 256, 256, 0, s2>>>();
    cudaEventRecord(ev_side, s2);

    // Main: Q projection (concurrent with side kv/reduce), then ln_q
    gemm_mma_kernel<<<ggrid, 256, GEMM_SMEM>>>(query, Wq, bq, pq);
    ln_elu_kernel<<<MTOT, 256>>>(pq, gq, betaq);

    // Join side stream, then attention + output projection
    cudaStreamWaitEvent(0, ev_side, 0);
    attn_mma_kernel<<<dim3(BH_, NQ_ / 64), 256>>>();
    gemm_mma_kernel<<<ggrid, 256, GEMM_SMEM>>>(pattn, Wo, bo, out);
}

// round 16
// speedup vs baseline: 1.0416x; 1.0005x over previous
#include <cuda_runtime.h>
#include <cstdint>

// Problem constants
#define E_   1024
#define H_   16
#define D_   64
#define B_   4
#define NQ_  4096
#define NK_  4096
#define MTOT (B_*NQ_)      // 16384 rows for all projections
#define BH_  (B_*H_)       // 64
#define NSPLIT 32          // split-K partitions for KV reduction
#define MHALF (MTOT/2)     // 8192 rows = batches {0,1}

// ---------------- scratch (device globals; no allocation APIs) ----------------
__device__ float g_q[(size_t)MTOT * E_];      // Q projection (LN+elu'd in place)
__device__ float g_k[(size_t)MTOT * E_];      // K projection (LN+elu'd in place)
__device__ float g_v[(size_t)MTOT * E_];
__device__ float g_attn[(size_t)MTOT * E_];
__device__ float g_kvp[(size_t)NSPLIT * BH_ * D_ * D_];
__device__ float g_ksp[(size_t)NSPLIT * BH_ * D_];
__device__ float g_kv[(size_t)BH_ * D_ * D_];
__device__ float g_ksum[(size_t)BH_ * D_];

// =====================================================================
// Helpers (sm_80+ base target features only)
// =====================================================================
__device__ __forceinline__ uint32_t smem_u32(const void* p) {
    uint32_t a;
    asm("{ .reg .u64 t; cvta.to.shared.u64 t, %1; cvt.u32.u64 %0, t; }"
        : "=r"(a) : "l"(p));
    return a;
}

__device__ __forceinline__ void cp_async16(uint32_t saddr, const void* gaddr) {
    asm volatile("cp.async.cg.shared.global [%0], [%1], 16;"
                 :: "r"(saddr), "l"(gaddr));
}
__device__ __forceinline__ void cp_commit() {
    asm volatile("cp.async.commit_group;" ::: "memory");
}
template <int N>
__device__ __forceinline__ void cp_wait() {
    asm volatile("cp.async.wait_group %0;" :: "n"(N) : "memory");
}

__device__ __forceinline__ uint32_t f2tf32(float f) {
    uint32_t u;
    asm("cvt.rna.tf32.f32 %0, %1;" : "=r"(u) : "f"(f));
    return u;
}

__device__ __forceinline__ void mma_tf32(
    float& d0, float& d1, float& d2, float& d3,
    uint32_t a0, uint32_t a1, uint32_t a2, uint32_t a3,
    uint32_t b0, uint32_t b1)
{
    asm volatile(
        "mma.sync.aligned.m16n8k8.row.col.f32.tf32.tf32.f32 "
        "{%0,%1,%2,%3}, {%4,%5,%6,%7}, {%8,%9}, {%0,%1,%2,%3};"
        : "+f"(d0), "+f"(d1), "+f"(d2), "+f"(d3)
        : "r"(a0), "r"(a1), "r"(a2), "r"(a3), "r"(b0), "r"(b1));
}

// =====================================================================
// tf32 GEMM (round-7 kernel, byte-exact): C[m,n]=sum_k X[m,k]W[n,k]+bias[n]
// =====================================================================
#define BM 128
#define BN 128
#define BK 32
#define NKT (E_/BK)
#define ASTR 36
#define TILEF (128*ASTR)
#define GEMM_SMEM (4*TILEF*4)   // 73728 bytes

__global__ void __launch_bounds__(256, 2)
gemm_mma_kernel(const float* __restrict__ X, const float* __restrict__ W,
                const float* __restrict__ bias, float* __restrict__ C)
{
    extern __shared__ float smf[];
    const uint32_t sbase = smem_u32(smf);
    const int tid = threadIdx.x;
    const int wid = tid >> 5;
    const int lane = tid & 31;
    const int g  = lane >> 2;
    const int t4 = lane & 3;
    const int wm = (wid >> 2) * 64;
    const int wn = (wid & 3) * 32;
    const int bm = blockIdx.x * BM;
    const int bn = blockIdx.y * BN;

    const int srow = tid >> 3;
    const int sc4  = (tid & 7) * 4;

    float acc[4][4][4];
#pragma unroll
    for (int i = 0; i < 4; i++)
#pragma unroll
        for (int j = 0; j < 4; j++)
#pragma unroll
            for (int r = 0; r < 4; r++) acc[i][j][r] = 0.0f;

    auto prefetch = [&](int kt, int buf) {
        const int k0 = kt * BK;
        const uint32_t aoff = sbase + (uint32_t)(buf * TILEF) * 4u;
        const uint32_t boff = sbase + (uint32_t)((2 + buf) * TILEF) * 4u;
#pragma unroll
        for (int l = 0; l < 4; l++) {
            int row = srow + l * 32;
            cp_async16(aoff + (row * ASTR + sc4) * 4,
                       X + (size_t)(bm + row) * E_ + k0 + sc4);
            cp_async16(boff + (row * ASTR + sc4) * 4,
                       W + (size_t)(bn + row) * E_ + k0 + sc4);
        }
        cp_commit();
    };

    prefetch(0, 0);

    for (int kt = 0; kt < NKT; kt++) {
        const int buf = kt & 1;
        if (kt + 1 < NKT) {
            prefetch(kt + 1, buf ^ 1);
            cp_wait<1>();
        } else {
            cp_wait<0>();
        }
        __syncthreads();

        const float* As = smf + buf * TILEF;
        const float* Bs = smf + (2 + buf) * TILEF;

#pragma unroll
        for (int ks = 0; ks < 4; ks++) {
            const int kk = ks * 8;
            uint32_t bf[4][2];
#pragma unroll
            for (int nf = 0; nf < 4; nf++) {
                const float* bp = Bs + (wn + nf * 8 + g) * ASTR + kk + t4;
                bf[nf][0] = f2tf32(bp[0]);
                bf[nf][1] = f2tf32(bp[4]);
            }
#pragma unroll
            for (int mf = 0; mf < 4; mf++) {
                const float* ap = As + (wm + mf * 16 + g) * ASTR + kk + t4;
                uint32_t a0 = f2tf32(ap[0]);
                uint32_t a1 = f2tf32(ap[8 * ASTR]);
                uint32_t a2 = f2tf32(ap[4]);
                uint32_t a3 = f2tf32(ap[8 * ASTR + 4]);
#pragma unroll
                for (int nf = 0; nf < 4; nf++)
                    mma_tf32(acc[mf][nf][0], acc[mf][nf][1],
                             acc[mf][nf][2], acc[mf][nf][3],
                             a0, a1, a2, a3, bf[nf][0], bf[nf][1]);
            }
        }
        __syncthreads();
    }

#pragma unroll
    for (int nf = 0; nf < 4; nf++) {
        const int col = bn + wn + nf * 8 + t4 * 2;
        const float2 b2 = *(const float2*)(bias + col);
#pragma unroll
        for (int mf = 0; mf < 4; mf++) {
            const int row0 = bm + wm + mf * 16 + g;
            float2 v0, v1;
            v0.x = acc[mf][nf][0] + b2.x;
            v0.y = acc[mf][nf][1] + b2.y;
            v1.x = acc[mf][nf][2] + b2.x;
            v1.y = acc[mf][nf][3] + b2.y;
            *(float2*)(C + (size_t)row0 * E_ + col) = v0;
            *(float2*)(C + (size_t)(row0 + 8) * E_ + col) = v1;
        }
    }
}

// ---------------- LayerNorm + elu + 1 (one block per row) ----------------
__global__ __launch_bounds__(256)
void ln_elu_kernel(float* __restrict__ X, const float* __restrict__ gamma,
                   const float* __restrict__ beta) {
    const int row = blockIdx.x;
    const int t = threadIdx.x;
    float* xr = X + (size_t)row * E_;

    float v[4];
#pragma unroll
    for (int i = 0; i < 4; i++) v[i] = xr[t + i * 256];

    __shared__ float red[8];
    float s = v[0] + v[1] + v[2] + v[3];
#pragma unroll
    for (int o = 16; o > 0; o >>= 1) s += __shfl_xor_sync(0xffffffffu, s, o);
    if ((t & 31) == 0) red[t >> 5] = s;
    __syncthreads();
    float tot = red[0] + red[1] + red[2] + red[3] + red[4] + red[5] + red[6] + red[7];
    float mean = tot * (1.0f / E_);
    __syncthreads();

    float d0 = v[0] - mean, d1 = v[1] - mean, d2 = v[2] - mean, d3 = v[3] - mean;
    float s2 = d0 * d0 + d1 * d1 + d2 * d2 + d3 * d3;
#pragma unroll
    for (int o = 16; o > 0; o >>= 1) s2 += __shfl_xor_sync(0xffffffffu, s2, o);
    if ((t & 31) == 0) red[t >> 5] = s2;
    __syncthreads();
    float var = (red[0] + red[1] + red[2] + red[3] + red[4] + red[5] + red[6] + red[7]) * (1.0f / E_);
    float rstd = rsqrtf(var + 1e-5f);

    float dd[4] = {d0, d1, d2, d3};
#pragma unroll
    for (int i = 0; i < 4; i++) {
        int col = t + i * 256;
        float y = dd[i] * rstd * gamma[col] + beta[col];
        xr[col] = (y > 0.0f) ? (y + 1.0f) : expf(y);
    }
}

// ---------------- KV reduction (SIMT; runs concurrently with GEMMs) ----------------
__global__ __launch_bounds__(256)
void kv_kernel() {
    const int bh = blockIdx.x;
    const int b = bh >> 4, h = bh & 15;
    const int split = blockIdx.y;
    const int t = threadIdx.x;
    const int tx = t & 15, ty = t >> 4;

    __shared__ float Ks[64][68];
    __shared__ float Vs[64][68];

    const float* kbase = g_k + (size_t)(b * NK_) * E_ + h * D_;
    const float* vbase = g_v + (size_t)(b * NK_) * E_ + h * D_;

    float acc[4][4];
#pragma unroll
    for (int i = 0; i < 4; i++)
#pragma unroll
        for (int j = 0; j < 4; j++) acc[i][j] = 0.0f;
    float ks_local = 0.0f;

    for (int sblk = 0; sblk < 2; sblk++) {
        int n0 = split * 128 + sblk * 64;
#pragma unroll
        for (int l = 0; l < 4; l++) {
            int lin = t + l * 256;
            int r = lin >> 4;
            int c4 = (lin & 15) * 4;
            *(float4*)&Ks[r][c4] = *(const float4*)(kbase + (size_t)(n0 + r) * E_ + c4);
            *(float4*)&Vs[r][c4] = *(const float4*)(vbase + (size_t)(n0 + r) * E_ + c4);
        }
        __syncthreads();
#pragma unroll 4
        for (int n = 0; n < 64; n++) {
            float a[4], bb[4];
            *(float4*)a  = *(const float4*)&Ks[n][ty * 4];
            *(float4*)bb = *(const float4*)&Vs[n][tx * 4];
#pragma unroll
            for (int i = 0; i < 4; i++)
#pragma unroll
                for (int j = 0; j < 4; j++)
                    acc[i][j] += a[i] * bb[j];
        }
        if (t < 64) {
            float ss = 0.0f;
#pragma unroll 4
            for (int n = 0; n < 64; n++) ss += Ks[n][t];
            ks_local += ss;
        }
        __syncthreads();
    }

    float* outp = g_kvp + ((size_t)(split * BH_ + bh)) * (D_ * D_);
#pragma unroll
    for (int i = 0; i < 4; i++)
#pragma unroll
        for (int j = 0; j < 4; j++)
            outp[(ty * 4 + i) * D_ + tx * 4 + j] = acc[i][j];
    if (t < 64) g_ksp[(size_t)(split * BH_ + bh) * D_ + t] = ks_local;
}

// ---------------- reduce split-K partials ----------------
__global__ __launch_bounds__(256)
void reduce_kv_kernel() {
    int idx = blockIdx.x * blockDim.x + threadIdx.x;
    const int NKV = BH_ * D_ * D_;
    const int NKS = BH_ * D_;
    if (idx < NKV) {
        float s = 0.0f;
#pragma unroll
        for (int sp = 0; sp < NSPLIT; sp++)
            s += g_kvp[(size_t)sp * NKV + idx];
        g_kv[idx] = s;
    } else if (idx < NKV + NKS) {
        int j = idx - NKV;
        float s = 0.0f;
#pragma unroll
        for (int sp = 0; sp < NSPLIT; sp++)
            s += g_ksp[(size_t)sp * NKS + j];
        g_ksum[j] = s;
    }
}

// =====================================================================
// Attention apply via tensor cores (round-13; bh0 offset for batch split):
// per (b,h), 64-row q-tile: num = Q'[64x64] @ KV[64x64], den = Q'.ksum
// =====================================================================
#define QSTR 68

__global__ void __launch_bounds__(256)
attn_mma_kernel(int bh0)
{
    __shared__ float Qs[64 * QSTR];
    __shared__ float KVT[64 * QSTR];
    __shared__ float ksums[64];

    const int bh = bh0 + blockIdx.x;
    const int b = bh >> 4, h = bh & 15;
    const int n0 = blockIdx.y * 64;
    const int t = threadIdx.x;
    const int wid = t >> 5, lane = t & 31;
    const int g = lane >> 2, t4 = lane & 3;
    const int wq = wid >> 1;
    const int wn = (wid & 1) * 32;

    if (t < 64) ksums[t] = g_ksum[(size_t)bh * D_ + t];

#pragma unroll
    for (int l = 0; l < 4; l++) {
        int lin = t + l * 256;
        int r = lin >> 4;
        int c4 = (lin & 15) * 4;
        *(float4*)&Qs[r * QSTR + c4] =
            *(const float4*)(g_q + (size_t)(b * NQ_ + n0 + r) * E_ + h * D_ + c4);
    }
#pragma unroll
    for (int l = 0; l < 4; l++) {
        int lin = t + l * 256;
        int rd = lin >> 4;
        int c4 = (lin & 15) * 4;
        float4 kvx = *(const float4*)(g_kv + (size_t)bh * (D_ * D_) + rd * D_ + c4);
        KVT[(c4 + 0) * QSTR + rd] = kvx.x;
        KVT[(c4 + 1) * QSTR + rd] = kvx.y;
        KVT[(c4 + 2) * QSTR + rd] = kvx.z;
        KVT[(c4 + 3) * QSTR + rd] = kvx.w;
    }
    __syncthreads();

    float acc[4][4];
#pragma unroll
    for (int j = 0; j < 4; j++)
#pragma unroll
        for (int r = 0; r < 4; r++) acc[j][r] = 0.0f;

#pragma unroll
    for (int ks = 0; ks < 8; ks++) {
        const int kk = ks * 8;
        const float* ap = &Qs[(wq * 16 + g) * QSTR + kk + t4];
        uint32_t a0 = f2tf32(ap[0]);
        uint32_t a1 = f2tf32(ap[8 * QSTR]);
        uint32_t a2 = f2tf32(ap[4]);
        uint32_t a3 = f2tf32(ap[8 * QSTR + 4]);
#pragma unroll
        for (int nf = 0; nf < 4; nf++) {
            const float* bp = &KVT[(wn + nf * 8 + g) * QSTR + kk + t4];
            mma_tf32(acc[nf][0], acc[nf][1], acc[nf][2], acc[nf][3],
                     a0, a1, a2, a3, f2tf32(bp[0]), f2tf32(bp[4]));
        }
    }

    const int r0 = wq * 16 + g, r1 = r0 + 8;
    float dp0 = 0.0f, dp1 = 0.0f;
#pragma unroll
    for (int i = 0; i < 16; i++) {
        int d = t4 * 16 + i;
        float kd = ksums[d];
        dp0 += Qs[r0 * QSTR + d] * kd;
        dp1 += Qs[r1 * QSTR + d] * kd;
    }
    dp0 += __shfl_xor_sync(0xffffffffu, dp0, 1);
    dp0 += __shfl_xor_sync(0xffffffffu, dp0, 2);
    dp1 += __shfl_xor_sync(0xffffffffu, dp1, 1);
    dp1 += __shfl_xor_sync(0xffffffffu, dp1, 2);
    const float inv0 = 1.0f / (dp0 + 1e-8f);
    const float inv1 = 1.0f / (dp1 + 1e-8f);

#pragma unroll
    for (int nf = 0; nf < 4; nf++) {
        const int e0 = wn + nf * 8 + t4 * 2;
        float2 o0, o1;
        o0.x = acc[nf][0] * inv0; o0.y = acc[nf][1] * inv0;
        o1.x = acc[nf][2] * inv1; o1.y = acc[nf][3] * inv1;
        *(float2*)(g_attn + (size_t)(b * NQ_ + n0 + r0) * E_ + h * D_ + e0) = o0;
        *(float2*)(g_attn + (size_t)(b * NQ_ + n0 + r1) * E_ + h * D_ + e0) = o1;
    }
}

// ---------------- host launcher (fork/join + batch-split Q tail) ----------------
extern "C" void kernel_launch(void* const* d_in, const int* in_sizes, int n_in,
                              void* d_out, int out_size) {
    (void)in_sizes; (void)n_in; (void)out_size;
    const float* query = (const float*)d_in[0];
    const float* key   = (const float*)d_in[1];
    const float* value = (const float*)d_in[2];
    const float* Wq = (const float*)d_in[3];
    const float* bq = (const float*)d_in[4];
    const float* Wk = (const float*)d_in[5];
    const float* bk = (const float*)d_in[6];
    const float* Wv = (const float*)d_in[7];
    const float* bv = (const float*)d_in[8];
    const float* Wo = (const float*)d_in[9];
    const float* bo = (const float*)d_in[10];
    const float* gq    = (const float*)d_in[11];
    const float* betaq = (const float*)d_in[12];
    const float* gk    = (const float*)d_in[13];
    const float* betak = (const float*)d_in[14];
    float* out = (float*)d_out;

    float *pq, *pk, *pv, *pattn;
    cudaGetSymbolAddress((void**)&pq, g_q);
    cudaGetSymbolAddress((void**)&pk, g_k);
    cudaGetSymbolAddress((void**)&pv, g_v);
    cudaGetSymbolAddress((void**)&pattn, g_attn);

    cudaFuncSetAttribute(gemm_mma_kernel,
                         cudaFuncAttributeMaxDynamicSharedMemorySize, GEMM_SMEM);

    // One-time resource init (first call is the non-capturing correctness
    // run; work launched per call is identical every time).
    static cudaStream_t s2 = nullptr;
    static cudaEvent_t ev_k = nullptr, ev_v = nullptr, ev_q1 = nullptr,
                       ev_side = nullptr, ev_a1 = nullptr;
    if (s2 == nullptr) {
        cudaStreamCreateWithFlags(&s2, cudaStreamNonBlocking);
        cudaEventCreateWithFlags(&ev_k, cudaEventDisableTiming);
        cudaEventCreateWithFlags(&ev_v, cudaEventDisableTiming);
        cudaEventCreateWithFlags(&ev_q1, cudaEventDisableTiming);
        cudaEventCreateWithFlags(&ev_side, cudaEventDisableTiming);
        cudaEventCreateWithFlags(&ev_a1, cudaEventDisableTiming);
    }

    dim3 gfull(MTOT / BM, E_ / BN);    // (128, 8)
    dim3 ghalf(MHALF / BM, E_ / BN);   // (64, 8)

    // Main: K projection
    gemm_mma_kernel<<<gfull, 256, GEMM_SMEM>>>(key, Wk, bk, pk);
    cudaEventRecord(ev_k, 0);
    // Main: V projection (concurrent with side ln_k)
    gemm_mma_kernel<<<gfull, 256, GEMM_SMEM>>>(value, Wv, bv, pv);
    cudaEventRecord(ev_v, 0);

    // Side: ln_k after K-GEMM; kv after V-GEMM; reduce after kv
    cudaStreamWaitEvent(s2, ev_k, 0);
    ln_elu_kernel<<<MTOT, 256, 0, s2>>>(pk, gk, betak);
    cudaStreamWaitEvent(s2, ev_v, 0);
    kv_kernel<<<dim3(BH_, NSPLIT), 256, 0, s2>>>();
    reduce_kv_kernel<<<(BH_ * D_ * D_ + BH_ * D_ + 255) / 256, 256, 0, s2>>>();
    cudaEventRecord(ev_side, s2);

    // Main: Q projection, split by batch halves
    gemm_mma_kernel<<<ghalf, 256, GEMM_SMEM>>>(query, Wq, bq, pq);
    cudaEventRecord(ev_q1, 0);
    gemm_mma_kernel<<<ghalf, 256, GEMM_SMEM>>>(
        query + (size_t)MHALF * E_, Wq, bq, pq + (size_t)MHALF * E_);

    // Side: first-half LN + attention (bh 0..31), concurrent with Qg2
    cudaStreamWaitEvent(s2, ev_q1, 0);
    ln_elu_kernel<<<MHALF, 256, 0, s2>>>(pq, gq, betaq);
    attn_mma_kernel<<<dim3(BH_ / 2, NQ_ / 64), 256, 0, s2>>>(0);
    cudaEventRecord(ev_a1, s2);

    // Main: second-half LN + attention (bh 32..63)
    ln_elu_kernel<<<MHALF, 256>>>(pq + (size_t)MHALF * E_, gq, betaq);
    cudaStreamWaitEvent(0, ev_side, 0);
    attn_mma_kernel<<<dim3(BH_ / 2, NQ_ / 64), 256>>>(BH_ / 2);

    // Join first-half attention, then output projection -> d_out
    cudaStreamWaitEvent(0, ev_a1, 0);
    gemm_mma_kernel<<<gfull, 256, GEMM_SMEM>>>(pattn, Wo, bo, out);
}